// round 7
// baseline (speedup 1.0000x reference)
#include <cuda_runtime.h>

#define B  32
#define L  1024
#define D  512
#define NN 512

// 8 partial-sum planes of sum_l(i - j) over L-eighths: [8][B][D]
__device__ float g_part[8 * B * D];
// transposed mean-diff: g_mdT[d][b]  (64 KB, L2-hot)
__device__ float g_mdT[D * B];
// 16 partial GEMV planes: g_up[dc][b][n]  (1 MB, L2-hot)
__device__ float g_up[16 * B * NN];
// DCE-defeating sink for the W prefetch
__device__ float g_sink;

// ---------------------------------------------------------------------------
// Kernel 1 (unchanged): part[lo][b][d] = sum_{l in eighth} (i - j)
// 1024 blocks x 256 thr, all resident. Full-warp 512B LDG.128 rows, __ldcs.
// Side job: prefetch W (1 MB) into L2.
// ---------------------------------------------------------------------------
__global__ void __launch_bounds__(256, 8) mean_diff_kernel(
    const float* __restrict__ gi, const float* __restrict__ gj,
    const float* __restrict__ W)
{
    const int blk = blockIdx.x;
    const int b   = blk >> 5;
    const int r   = blk & 31;
    const int dt  = r >> 3;           // 128-float d tile (4 per D)
    const int lo  = r & 7;            // L eighth
    const int tid = threadIdx.x;
    const int dq  = tid & 31;
    const int lg  = tid >> 5;

    if (tid < 64) {
        float4 w = __ldcg(((const float4*)W) + blk * 64 + tid);
        float t = w.x + w.y + w.z + w.w;
        if (__float_as_int(t) == 0x7f800001)  // never true in practice
            g_sink = t;
    }

    const int rowq = D / 4;
    const float4* pi = (const float4*)(gi + (size_t)b * L * D) + dt * 32 + dq;
    const float4* pj = (const float4*)(gj + (size_t)b * L * D) + dt * 32 + dq;

    const int l0 = lo * 128 + lg * 16;
    float4 acc = make_float4(0.f, 0.f, 0.f, 0.f);
    #pragma unroll
    for (int rr = 0; rr < 16; rr++) {
        size_t off = (size_t)(l0 + rr) * rowq;
        float4 a = __ldcs(pi + off);
        float4 c = __ldcs(pj + off);
        acc.x += a.x - c.x;
        acc.y += a.y - c.y;
        acc.z += a.z - c.z;
        acc.w += a.w - c.w;
    }

    __shared__ float4 s[256];
    s[tid] = acc;
    __syncthreads();

    #pragma unroll
    for (int stride = 128; stride >= 32; stride >>= 1) {
        if (tid < stride) {
            float4 o = s[tid + stride];
            s[tid].x += o.x; s[tid].y += o.y; s[tid].z += o.z; s[tid].w += o.w;
        }
        __syncthreads();
    }

    if (tid < 32)
        ((float4*)(g_part + lo * B * D + b * D + dt * 128))[tid] = s[tid];
}

// ---------------------------------------------------------------------------
// Kernel 2: g_mdT[d][b] = (1/L) * sum_pl g_part[pl][b][d]
// 64 blocks x 256 thr; coalesced plane reads, scattered (cheap) stores.
// ---------------------------------------------------------------------------
__global__ void __launch_bounds__(256) reduce_md_kernel()
{
    const int t = blockIdx.x * 256 + threadIdx.x;   // t = b*D + d
    const int b = t >> 9;
    const int d = t & 511;

    float v = 0.f;
    #pragma unroll
    for (int pl = 0; pl < 8; pl++)
        v += g_part[pl * B * D + t];

    g_mdT[d * B + b] = v * (1.0f / (float)L);
}

// ---------------------------------------------------------------------------
// Kernel 3: partial GEMV with FULL 32-batch reuse of W.
// Grid: 16 d-chunks x 16 n-chunks = 256 blocks x 256 thr.
// Per block: stage W[32d][32n] (4KB) + mdT[32d][32b] (4KB) in smem, then
// each thread (n = tid&31, bg = tid>>5) accumulates 4 batches over 32 d:
//   per d: 1 conflict-free LDS row (sW) + 1 float4 broadcast LDS (smd) + 4 FMA.
// Writes g_up[dc][b][n]. Total W L2 traffic: 1 MB (was 16 MB).
// ---------------------------------------------------------------------------
__global__ void __launch_bounds__(256) gemv_partial_kernel(
    const float* __restrict__ W)
{
    const int blk = blockIdx.x;
    const int dc  = blk >> 4;        // d-chunk (32 rows)
    const int nc  = blk & 15;        // n-chunk (32 cols)
    const int tid = threadIdx.x;

    __shared__ float sW[32][32];     // [d][n]
    __shared__ float smd[32][32];    // [d][b]

    #pragma unroll
    for (int k = 0; k < 4; k++) {
        int e = k * 256 + tid;
        int dd = e >> 5;
        int c  = e & 31;
        sW[dd][c]  = W[(size_t)(dc * 32 + dd) * NN + nc * 32 + c];
        smd[dd][c] = g_mdT[(dc * 32 + dd) * B + c];
    }
    __syncthreads();

    const int n  = tid & 31;
    const int bg = tid >> 5;         // 8 groups x 4 batches

    float4 u = make_float4(0.f, 0.f, 0.f, 0.f);
    #pragma unroll
    for (int d = 0; d < 32; d++) {
        float  w = sW[d][n];
        float4 m = *(const float4*)&smd[d][bg * 4];
        u.x = fmaf(m.x, w, u.x);
        u.y = fmaf(m.y, w, u.y);
        u.z = fmaf(m.z, w, u.z);
        u.w = fmaf(m.w, w, u.w);
    }

    float* up = g_up + dc * B * NN + (bg * 4) * NN + nc * 32 + n;
    up[0]      = u.x;
    up[NN]     = u.y;
    up[2 * NN] = u.z;
    up[3 * NN] = u.w;
}

// ---------------------------------------------------------------------------
// Kernel 4: out[b][n] = 0.5*(relu(u+bias) + relu(bias-u)),
//           u = sum over 16 d-chunk partials. 64 blocks x 256 thr.
// ---------------------------------------------------------------------------
__global__ void __launch_bounds__(256) combine_kernel(
    const float* __restrict__ bias, float* __restrict__ out)
{
    const int t = blockIdx.x * 256 + threadIdx.x;   // t = b*NN + n
    const int n = t & (NN - 1);

    float u = 0.f;
    #pragma unroll
    for (int dcc = 0; dcc < 16; dcc++)
        u += g_up[dcc * B * NN + t];

    float bv = bias[n];
    out[t] = 0.5f * (fmaxf(u + bv, 0.f) + fmaxf(bv - u, 0.f));
}

extern "C" void kernel_launch(void* const* d_in, const int* in_sizes, int n_in,
                              void* d_out, int out_size)
{
    const float* gi   = (const float*)d_in[0];   // i     [B, L, D]
    const float* gj   = (const float*)d_in[1];   // j     [B, L, D]
    const float* W    = (const float*)d_in[2];   // W_agg [D, NN]
    const float* bias = (const float*)d_in[3];   // b_agg [NN]
    float* out = (float*)d_out;                  // [B, NN]

    mean_diff_kernel<<<1024, 256>>>(gi, gj, W);
    reduce_md_kernel<<<64, 256>>>();
    gemv_partial_kernel<<<256, 256>>>(W);
    combine_kernel<<<64, 256>>>(bias, out);
}